// round 16
// baseline (speedup 1.0000x reference)
#include <cuda_runtime.h>
#include <cuda_fp16.h>
#include <cstdint>
#include <math.h>

#define BB 8
#define TT 1024
#define DD 1024
#define HH 16
#define HS 64
#define NE 8
#define NTOK (BB*TT)        // 8192
#define DFF 4096
#define LN_EPS 1e-5f

// ---------------- scratch (device globals; no runtime allocation) ----------------
__device__ __half g_q[(size_t)BB*HH*TT*HS];      // fp16, Q pre-scaled by 2^-5
__device__ __half g_k[(size_t)BB*HH*TT*HS];
__device__ __half g_v[(size_t)BB*HH*TT*HS];
__device__ __half g_attn[(size_t)NTOK*DD];       // fp16 attention output
__device__ __half g_h[(size_t)NTOK*2*DFF];       // fp16 (post-relu), rowid = tok*2+slot
__device__ __half g_y[(size_t)NTOK*2*DD];        // fp16 expert outputs
__device__ float  g_wtok[NTOK*2];
__device__ int    g_rows[NE*NTOK];
__device__ int    g_cnt[NE];
__device__ __half g_xt[(size_t)NTOK*DD];         // fp16 of x
__device__ __half g_w1[(size_t)NE*DD*DFF];       // W1 fp16, native [e][k][n]
__device__ __half g_w2[(size_t)NE*DFF*DD];       // W2 fp16, native [e][k][n]
__device__ __half g_wqkv[(size_t)3*HH*DD*HS];    // native [part][h][k][hs] fp16

// ---------------- helpers ----------------
__device__ __forceinline__ uint32_t smem_u32(const void* p) {
    uint32_t a;
    asm("{ .reg .u64 t; cvta.to.shared.u64 t, %1; cvt.u32.u64 %0, t; }" : "=r"(a) : "l"(p));
    return a;
}
#define SWZ(b) ((b) ^ (((b) >> 3) & 0x70))

__device__ __forceinline__ void mma_f16(float* c,
    uint32_t a0, uint32_t a1, uint32_t a2, uint32_t a3,
    uint32_t b0, uint32_t b1)
{
    asm volatile(
        "mma.sync.aligned.m16n8k16.row.col.f32.f16.f16.f32 "
        "{%0,%1,%2,%3}, {%4,%5,%6,%7}, {%8,%9}, {%0,%1,%2,%3};"
        : "+f"(c[0]), "+f"(c[1]), "+f"(c[2]), "+f"(c[3])
        : "r"(a0), "r"(a1), "r"(a2), "r"(a3), "r"(b0), "r"(b1));
}
__device__ __forceinline__ void ldsm_x4(uint32_t* r, uint32_t addr) {
    asm volatile("ldmatrix.sync.aligned.m8n8.x4.shared.b16 {%0,%1,%2,%3}, [%4];"
        : "=r"(r[0]), "=r"(r[1]), "=r"(r[2]), "=r"(r[3]) : "r"(addr));
}
__device__ __forceinline__ void ldsm_x4t(uint32_t* r, uint32_t addr) {
    asm volatile("ldmatrix.sync.aligned.m8n8.x4.trans.shared.b16 {%0,%1,%2,%3}, [%4];"
        : "=r"(r[0]), "=r"(r[1]), "=r"(r[2]), "=r"(r[3]) : "r"(addr));
}
#define CP_ASYNC16(dst, src) \
    asm volatile("cp.async.cg.shared.global [%0], [%1], 16;" :: "r"(dst), "l"((const void*)(src)))
#define CP_COMMIT() asm volatile("cp.async.commit_group;" ::: "memory")
#define CP_WAIT1() asm volatile("cp.async.wait_group 1;" ::: "memory")

__device__ __forceinline__ uint32_t h2u(float a, float b) {
    __half2 h = __floats2half2_rn(a, b);
    return *(uint32_t*)&h;
}
__device__ __forceinline__ uint32_t exp2_f16x2(float a, float b) {
    __half2 h = __floats2half2_rn(a, b);
    uint32_t u = *(uint32_t*)&h, r;
    asm("ex2.approx.f16x2 %0, %1;" : "=r"(r) : "r"(u));
    return r;
}

// GEMM smem: 3 stages x (A 16KB + B 16KB) = 96KB
#define ST_BYTES 16384
#define GEMM_SMEM (6 * ST_BYTES + 1024)

// ---------------- preprocessing ----------------
__global__ void zcnt_kernel() {
    if (threadIdx.x < NE) g_cnt[threadIdx.x] = 0;
}

// streaming fp32 -> fp16 copy, 8 elems/thread
__global__ __launch_bounds__(256) void wcvt_kernel(
    const float* __restrict__ in, __half* __restrict__ out)
{
    size_t i = ((size_t)blockIdx.x * 256 + threadIdx.x) * 8;
    float4 v0 = *(const float4*)(in + i);
    float4 v1 = *(const float4*)(in + i + 4);
    uint4 u = make_uint4(h2u(v0.x, v0.y), h2u(v0.z, v0.w),
                         h2u(v1.x, v1.y), h2u(v1.z, v1.w));
    *(uint4*)(out + i) = u;
}

// QKV weights: 3 parts in one launch, grid (512, 3)
__global__ __launch_bounds__(256) void wcvt_qkv_kernel(
    const float* __restrict__ Wq, const float* __restrict__ Wk,
    const float* __restrict__ Wv, __half* __restrict__ out)
{
    const size_t PART = (size_t)HH * DD * HS;
    int part = blockIdx.y;
    const float* in = (part == 0) ? Wq : (part == 1) ? Wk : Wv;
    size_t i = ((size_t)blockIdx.x * 256 + threadIdx.x) * 8;
    float4 v0 = *(const float4*)(in + i);
    float4 v1 = *(const float4*)(in + i + 4);
    uint4 u = make_uint4(h2u(v0.x, v0.y), h2u(v0.z, v0.w),
                         h2u(v1.x, v1.y), h2u(v1.z, v1.w));
    *(uint4*)(out + part * PART + i) = u;
}

// ---------------- fused routing + x cvt: warp per token, Wg smem-transposed ----
__global__ __launch_bounds__(256) void routex_kernel(
    const float* __restrict__ X, const float* __restrict__ Wg)
{
    __shared__ float4 wgt[NE][256];   // WgT: [e][d/4] float4, 32KB
    const int tid = threadIdx.x;
    const float4* Wg4 = (const float4*)Wg;
#pragma unroll
    for (int i = 0; i < 8; i++) {
        int fi = tid + i * 256;            // 0..2047
        float4 v = Wg4[fi];
        int d = fi >> 1;
        int e0 = (fi & 1) * 4;
        int q = d >> 2, c = d & 3;
        ((float*)&wgt[e0 + 0][q])[c] = v.x;
        ((float*)&wgt[e0 + 1][q])[c] = v.y;
        ((float*)&wgt[e0 + 2][q])[c] = v.z;
        ((float*)&wgt[e0 + 3][q])[c] = v.w;
    }
    __syncthreads();

    int tok = (blockIdx.x * 256 + tid) >> 5;
    int lane = tid & 31;
    const float* xr = X + (size_t)tok * DD;
    __half* xo = g_xt + (size_t)tok * DD;
    float p[NE];
#pragma unroll
    for (int e = 0; e < NE; e++) p[e] = 0.f;
#pragma unroll
    for (int it = 0; it < 8; it++) {
        int d4 = lane + it * 32;
        float4 xv = ((const float4*)xr)[d4];
        *(uint2*)(xo + d4 * 4) = make_uint2(h2u(xv.x, xv.y), h2u(xv.z, xv.w));
#pragma unroll
        for (int e = 0; e < NE; e++) {
            float4 w = wgt[e][d4];
            p[e] += xv.x * w.x; p[e] += xv.y * w.y;
            p[e] += xv.z * w.z; p[e] += xv.w * w.w;
        }
    }
#pragma unroll
    for (int e = 0; e < NE; e++)
#pragma unroll
        for (int off = 16; off; off >>= 1)
            p[e] += __shfl_xor_sync(0xffffffffu, p[e], off);

    if (lane == 0) {
        int i0 = 0; float v0 = p[0];
#pragma unroll
        for (int e = 1; e < NE; e++) if (p[e] > v0) { v0 = p[e]; i0 = e; }
        int i1 = -1; float v1 = -INFINITY;
#pragma unroll
        for (int e = 0; e < NE; e++) if (e != i0 && p[e] > v1) { v1 = p[e]; i1 = e; }
        float e1v = expf(v1 - v0);
        float inv = 1.f / (1.f + e1v);
        g_wtok[tok * 2 + 0] = inv;
        g_wtok[tok * 2 + 1] = e1v * inv;
        int pos0 = atomicAdd(&g_cnt[i0], 1);
        g_rows[i0 * NTOK + pos0] = tok * 2;
        int pos1 = atomicAdd(&g_cnt[i1], 1);
        g_rows[i1 * NTOK + pos1] = tok * 2 + 1;
    }
}

// =======================================================================
// QKV GEMM: grid (64, 24), block 128 (4 warps, 64x64 warp tiles)
// B frags via ldsm.x4.trans; single barrier per chunk
// =======================================================================
__global__ __launch_bounds__(128) void qkv_tc_kernel()
{
    const int row0 = blockIdx.x * 128;
    const int by = blockIdx.y;
    const int part = by >> 3;
    const int h0 = (by & 7) * 2;
    __half* Out = (part == 0) ? g_q : (part == 1) ? g_k : g_v;
    const float qscale = (part == 0) ? 0.03125f : 1.0f;

    extern __shared__ char dynraw[];
    char* p = (char*)(((uintptr_t)dynraw + 1023) & ~(uintptr_t)1023);
    const uint32_t sb = smem_u32(p);
    const int tid = threadIdx.x;
    const int wid = tid >> 5, lane = tid & 31;
    const int wm = (wid & 1) * 64, wn = (wid >> 1) * 64;

    const int quad = lane >> 3, lr = lane & 7;
    const uint32_t a_rowb = (uint32_t)(wm + (quad & 1) * 8 + lr) * 128;
    const uint32_t a_boff = (uint32_t)(quad >> 1) * 16;
    const uint32_t xv = (uint32_t)lr << 4;
    const uint32_t hi16 = (uint32_t)((lane >> 4) & 1);
    const uint32_t bt_row = (uint32_t)(((lane >> 3) & 1) * 8 + lr) * 128;
    const uint32_t subw = (uint32_t)(wn >> 6) * 8192;

    float acc[4][8][4];
#pragma unroll
    for (int i = 0; i < 4; i++)
#pragma unroll
        for (int j = 0; j < 8; j++)
#pragma unroll
            for (int q = 0; q < 4; q++) acc[i][j][q] = 0.f;

    const int NCH = DD / 64;
    auto issue = [&](int c) {
        int k0 = c * 64;
        int s = c % 3;
        uint32_t ab = sb + s * ST_BYTES;
        uint32_t bb = sb + 3 * ST_BYTES + s * ST_BYTES;
#pragma unroll
        for (int i = 0; i < 8; i++) {
            int idx = tid + i * 128;
            {
                int row = idx >> 3, c16 = idx & 7;
                const __half* asrc = g_xt + (size_t)(row0 + row) * DD + k0 + c16 * 8;
                CP_ASYNC16(ab + SWZ(row * 128 + c16 * 16), asrc);
            }
            {
                int sub = idx >> 9, rem = idx & 511;
                int r = rem >> 3, c16 = rem & 7;
                const __half* bsrc = g_wqkv +
                    ((size_t)(part * HH + h0 + sub) * DD + k0 + r) * HS + c16 * 8;
                CP_ASYNC16(bb + sub * 8192 + SWZ(r * 128 + c16 * 16), bsrc);
            }
        }
        CP_COMMIT();
    };
    issue(0); issue(1);

    for (int c = 0; c < NCH; c++) {
        CP_WAIT1();
        __syncthreads();
        if (c + 2 < NCH) issue(c + 2); else CP_COMMIT();
        const int s = c % 3;
        const uint32_t At = sb + s * ST_BYTES;
        const uint32_t Bt = sb + 3 * ST_BYTES + s * ST_BYTES + subw;
#pragma unroll
        for (int ks = 0; ks < 4; ks++) {
            uint32_t akoff = (((uint32_t)ks * 32) + a_boff) ^ xv;
            uint32_t trow = (uint32_t)(ks * 16) * 128 + bt_row;
            uint32_t af[4][4], bf4[4][4];
#pragma unroll
            for (int mt = 0; mt < 4; mt++)
                ldsm_x4(af[mt], At + a_rowb + mt * 2048 + akoff);
#pragma unroll
            for (int nt2 = 0; nt2 < 4; nt2++)
                ldsm_x4t(bf4[nt2], Bt + trow + ((((uint32_t)(nt2 * 2 + hi16)) * 16) ^ xv));
#pragma unroll
            for (int mt = 0; mt < 4; mt++)
#pragma unroll
                for (int nt2 = 0; nt2 < 4; nt2++) {
                    mma_f16(acc[mt][2 * nt2],     af[mt][0], af[mt][1], af[mt][2], af[mt][3],
                            bf4[nt2][0], bf4[nt2][1]);
                    mma_f16(acc[mt][2 * nt2 + 1], af[mt][0], af[mt][1], af[mt][2], af[mt][3],
                            bf4[nt2][2], bf4[nt2][3]);
                }
        }
    }

#pragma unroll
    for (int mt = 0; mt < 4; mt++) {
        int r = row0 + wm + mt * 16 + (lane >> 2);
        int r1 = r + 8;
        int b0i = r >> 10, t0 = r & 1023;
        int b1i = r1 >> 10, t1 = r1 & 1023;
#pragma unroll
        for (int nt = 0; nt < 8; nt++) {
            int n = wn + nt * 8 + 2 * (lane & 3);
            int head = h0 + (n >> 6);
            int hs = n & 63;
            *(uint32_t*)(Out + (((size_t)b0i * HH + head) * TT + t0) * HS + hs) =
                h2u(acc[mt][nt][0] * qscale, acc[mt][nt][1] * qscale);
            *(uint32_t*)(Out + (((size_t)b1i * HH + head) * TT + t1) * HS + hs) =
                h2u(acc[mt][nt][2] * qscale, acc[mt][nt][3] * qscale);
        }
    }
}

// =======================================================================
// MoE GEMM (G1: xt@W1+relu -> g_h fp16, else g_h@W2 -> g_y fp16)
// grid (64, Ntiles, NE), block 128; x4t B frags, single barrier per chunk
// =======================================================================
template<bool G1>
__global__ __launch_bounds__(128) void moe_tc_kernel(
    const float* __restrict__ biasfull)
{
    const int e = blockIdx.z;
    const int cnt = g_cnt[e];
    const int m0 = blockIdx.x * 128;
    if (m0 >= cnt) return;
    const int col0 = blockIdx.y * 128;
    const int KTOT = G1 ? DD : DFF;
    const int LDB  = G1 ? DFF : DD;
    const int LDO  = G1 ? DFF : DD;
    const int NCH = KTOT / 64;

    extern __shared__ char dynraw[];
    char* p = (char*)(((uintptr_t)dynraw + 1023) & ~(uintptr_t)1023);
    const uint32_t sb = smem_u32(p);

    __shared__ int rowids[128];
    const int tid = threadIdx.x;
    {
        int m = m0 + tid;
        rowids[tid] = (m < cnt) ? g_rows[e * NTOK + m] : -1;
    }
    __syncthreads();

    const int wid = tid >> 5, lane = tid & 31;
    const int wm = (wid & 1) * 64, wn = (wid >> 1) * 64;
    const int quad = lane >> 3, lr = lane & 7;
    const uint32_t a_rowb = (uint32_t)(wm + (quad & 1) * 8 + lr) * 128;
    const uint32_t a_boff = (uint32_t)(quad >> 1) * 16;
    const uint32_t xv = (uint32_t)lr << 4;
    const uint32_t hi16 = (uint32_t)((lane >> 4) & 1);
    const uint32_t bt_row = (uint32_t)(((lane >> 3) & 1) * 8 + lr) * 128;
    const uint32_t subw = (uint32_t)(wn >> 6) * 8192;

    float acc[4][8][4];
#pragma unroll
    for (int i = 0; i < 4; i++)
#pragma unroll
        for (int j = 0; j < 8; j++)
#pragma unroll
            for (int q = 0; q < 4; q++) acc[i][j][q] = 0.f;

    const __half* Wp = (G1 ? g_w1 : g_w2) + (size_t)e * ((size_t)DD * DFF);
    const float* bp = biasfull + (size_t)e * (G1 ? DFF : DD);

    auto issue = [&](int c) {
        int k0 = c * 64;
        int s = c % 3;
        uint32_t ab = sb + s * ST_BYTES;
        uint32_t bb = sb + 3 * ST_BYTES + s * ST_BYTES;
#pragma unroll
        for (int i = 0; i < 8; i++) {
            int idx = tid + i * 128;
            {
                int row = idx >> 3, c16 = idx & 7;
                int rid = rowids[row];
                const __half* asrc;
                if (G1) asrc = g_xt + (size_t)((rid >= 0) ? (rid >> 1) : 0) * DD + k0 + c16 * 8;
                else    asrc = g_h + (size_t)((rid >= 0) ? rid : 0) * DFF + k0 + c16 * 8;
                CP_ASYNC16(ab + SWZ(row * 128 + c16 * 16), asrc);
            }
            {
                int sub = idx >> 9, rem = idx & 511;
                int r = rem >> 3, c16 = rem & 7;
                const __half* bsrc = Wp + (size_t)(k0 + r) * LDB + col0 + sub * 64 + c16 * 8;
                CP_ASYNC16(bb + sub * 8192 + SWZ(r * 128 + c16 * 16), bsrc);
            }
        }
        CP_COMMIT();
    };
    issue(0); issue(1);

    for (int c = 0; c < NCH; c++) {
        CP_WAIT1();
        __syncthreads();
        if (c + 2 < NCH) issue(c + 2); else CP_COMMIT();
        const int s = c % 3;
        const uint32_t At = sb + s * ST_BYTES;
        const uint32_t Bt = sb + 3 * ST_BYTES + s * ST_BYTES + subw;
#pragma unroll
        for (int ks = 0; ks < 4; ks++) {
            uint32_t akoff = (((uint32_t)ks * 32) + a_boff) ^ xv;
            uint32_t trow = (uint32_t)(ks * 16) * 128 + bt_row;
            uint32_t af[4][4], bf4[4][4];
#pragma unroll
            for (int mt = 0; mt < 4; mt++)
                ldsm_x4(af[mt], At + a_rowb + mt * 2048 + akoff);
#pragma unroll
            for (int nt2 = 0; nt2 < 4; nt2++)
                ldsm_x4t(bf4[nt2], Bt + trow + ((((uint32_t)(nt2 * 2 + hi16)) * 16) ^ xv));
#pragma unroll
            for (int mt = 0; mt < 4; mt++)
#pragma unroll
                for (int nt2 = 0; nt2 < 4; nt2++) {
                    mma_f16(acc[mt][2 * nt2],     af[mt][0], af[mt][1], af[mt][2], af[mt][3],
                            bf4[nt2][0], bf4[nt2][1]);
                    mma_f16(acc[mt][2 * nt2 + 1], af[mt][0], af[mt][1], af[mt][2], af[mt][3],
                            bf4[nt2][2], bf4[nt2][3]);
                }
        }
    }

#pragma unroll
    for (int mt = 0; mt < 4; mt++) {
        int ml = wm + mt * 16 + (lane >> 2);
        int rid0 = rowids[ml];
        int rid1 = rowids[ml + 8];
#pragma unroll
        for (int nt = 0; nt < 8; nt++) {
            int n = col0 + wn + nt * 8 + 2 * (lane & 3);
            float bx = __ldg(&bp[n]), by = __ldg(&bp[n + 1]);
            if (G1) {
                if (rid0 >= 0) {
                    float v0 = fmaxf(acc[mt][nt][0] + bx, 0.f);
                    float v1 = fmaxf(acc[mt][nt][1] + by, 0.f);
                    *(uint32_t*)(g_h + (size_t)rid0 * LDO + n) = h2u(v0, v1);
                }
                if (rid1 >= 0) {
                    float v2 = fmaxf(acc[mt][nt][2] + bx, 0.f);
                    float v3 = fmaxf(acc[mt][nt][3] + by, 0.f);
                    *(uint32_t*)(g_h + (size_t)rid1 * LDO + n) = h2u(v2, v3);
                }
            } else {
                if (rid0 >= 0)
                    *(uint32_t*)(g_y + (size_t)rid0 * LDO + n) =
                        h2u(acc[mt][nt][0] + bx, acc[mt][nt][1] + by);
                if (rid1 >= 0)
                    *(uint32_t*)(g_y + (size_t)rid1 * LDO + n) =
                        h2u(acc[mt][nt][2] + bx, acc[mt][nt][3] + by);
            }
        }
    }
}

// =======================================================================
// fp16 tensor-core causal flash attention
// P in registers; K/V via ldmatrix.x4
// =======================================================================
#define ATT_SMEM (8192 + 2 * 16384)
#define L2E 1.44269504f

__global__ __launch_bounds__(128) void attn_tc_kernel()
{
    extern __shared__ char asc[];
    const uint32_t psb = smem_u32(asc);
    const uint32_t kvb = psb + 8192;

    const int bh = blockIdx.y;
    const int qt = 15 - blockIdx.x;
    const int tid = threadIdx.x;
    const int wid = tid >> 5, lane = tid & 31;
    const int gid = lane >> 2, tq = lane & 3;
    const int quad = lane >> 3, lr = lane & 7;
    const int qrow = wid * 16 + gid;
    const int qglob = qt * 64;

    const uint32_t a_rowb = (uint32_t)(wid * 16 + (quad & 1) * 8 + lr) * 128;
    const uint32_t a_boff = (uint32_t)(quad >> 1) * 16;
    const uint32_t b_boff = (uint32_t)((lane >> 3) & 1) * 16;
    const uint32_t xv = (uint32_t)lr << 4;
    const uint32_t hi16 = (uint32_t)((lane >> 4) & 1);
    const uint32_t kx_rowb = (hi16 * 8 + (uint32_t)lr) * 128;
    const uint32_t v_rowb = ((uint32_t)((lane >> 3) & 1) * 8 + (uint32_t)lr) * 128;

    auto issue_kv = [&](int kt) {
        int s = kt & 1;
        uint32_t kb = kvb + s * 16384;
        uint32_t vb = kb + 8192;
        const __half* kp = g_k + ((size_t)bh * TT + kt * 64) * HS;
        const __half* vp = g_v + ((size_t)bh * TT + kt * 64) * HS;
#pragma unroll
        for (int i = 0; i < 4; i++) {
            int idx = tid + i * 128;
            int r = idx >> 3, c16 = idx & 7;
            CP_ASYNC16(kb + SWZ(r * 128 + c16 * 16), kp + (size_t)r * HS + c16 * 8);
            CP_ASYNC16(vb + SWZ(r * 128 + c16 * 16), vp + (size_t)r * HS + c16 * 8);
        }
        CP_COMMIT();
    };

    {
        const __half* qp = g_q + ((size_t)bh * TT + qglob) * HS;
#pragma unroll
        for (int i = 0; i < 4; i++) {
            int idx = tid + i * 128;
            int r = idx >> 3, c16 = idx & 7;
            CP_ASYNC16(psb + SWZ(r * 128 + c16 * 16), qp + (size_t)r * HS + c16 * 8);
        }
        CP_COMMIT();
    }
    issue_kv(0);
    CP_WAIT1();
    __syncthreads();

    uint32_t qf[4][4];
#pragma unroll
    for (int ks = 0; ks < 4; ks++)
        ldsm_x4(qf[ks], psb + a_rowb + ((((uint32_t)ks * 32) + a_boff) ^ xv));

    float oacc[8][4];
#pragma unroll
    for (int i = 0; i < 8; i++)
#pragma unroll
        for (int j = 0; j < 4; j++) oacc[i][j] = 0.f;
    float m0 = -INFINITY, m1 = -INFINITY, l0 = 0.f, l1 = 0.f;

    for (int kt = 0; kt <= qt; kt++) {
        if (kt + 1 <= qt) issue_kv(kt + 1); else CP_COMMIT();
        CP_WAIT1();
        __syncthreads();
        const int s = kt & 1;
        const uint32_t Kb = kvb + s * 16384;
        const uint32_t Vb = Kb + 8192;

        float sacc[8][4];
#pragma unroll
        for (int nt = 0; nt < 8; nt++)
#pragma unroll
            for (int j = 0; j < 4; j++) sacc[nt][j] = 0.f;
#pragma unroll
        for (int ks = 0; ks < 4; ks++) {
            uint32_t bkoff = (((uint32_t)ks * 32) + b_boff) ^ xv;
#pragma unroll
            for (int nt2 = 0; nt2 < 4; nt2++) {
                uint32_t bf4[4];
                ldsm_x4(bf4, Kb + (uint32_t)(nt2 * 16) * 128 + kx_rowb + bkoff);
                mma_f16(sacc[2 * nt2],     qf[ks][0], qf[ks][1], qf[ks][2], qf[ks][3],
                        bf4[0], bf4[1]);
                mma_f16(sacc[2 * nt2 + 1], qf[ks][0], qf[ks][1], qf[ks][2], qf[ks][3],
                        bf4[2], bf4[3]);
            }
        }
        if (kt == qt) {
#pragma unroll
            for (int nt = 0; nt < 8; nt++) {
                int col = nt * 8 + 2 * tq;
                if (col     > qrow)     sacc[nt][0] = -INFINITY;
                if (col + 1 > qrow)     sacc[nt][1] = -INFINITY;
                if (col     > qrow + 8) sacc[nt][2] = -INFINITY;
                if (col + 1 > qrow + 8) sacc[nt][3] = -INFINITY;
            }
        }
        float r0 = -INFINITY, r1 = -INFINITY;
#pragma unroll
        for (int nt = 0; nt < 8; nt++) {
            r0 = fmaxf(r0, fmaxf(sacc[nt][0], sacc[nt][1]));
            r1 = fmaxf(r1, fmaxf(sacc[nt][2], sacc[nt][3]));
        }
        r0 = fmaxf(r0, __shfl_xor_sync(0xffffffffu, r0, 1));
        r0 = fmaxf(r0, __shfl_xor_sync(0xffffffffu, r0, 2));
        r1 = fmaxf(r1, __shfl_xor_sync(0xffffffffu, r1, 1));
        r1 = fmaxf(r1, __shfl_xor_sync(0xffffffffu, r1, 2));
        float mn0 = fmaxf(m0, r0), mn1 = fmaxf(m1, r1);
        float c0 = __expf(m0 - mn0), c1 = __expf(m1 - mn1);
        float ps0 = 0.f, ps1 = 0.f;
        uint32_t pu01[8], pu23[8];
#pragma unroll
        for (int nt = 0; nt < 8; nt++) {
            pu01[nt] = exp2_f16x2((sacc[nt][0] - mn0) * L2E, (sacc[nt][1] - mn0) * L2E);
            pu23[nt] = exp2_f16x2((sacc[nt][2] - mn1) * L2E, (sacc[nt][3] - mn1) * L2E);
            float2 f01 = __half22float2(*(__half2*)&pu01[nt]);
            float2 f23 = __half22float2(*(__half2*)&pu23[nt]);
            ps0 += f01.x + f01.y;
            ps1 += f23.x + f23.y;
        }
        ps0 += __shfl_xor_sync(0xffffffffu, ps0, 1);
        ps0 += __shfl_xor_sync(0xffffffffu, ps0, 2);
        ps1 += __shfl_xor_sync(0xffffffffu, ps1, 1);
        ps1 += __shfl_xor_sync(0xffffffffu, ps1, 2);
        l0 = l0 * c0 + ps0;
        l1 = l1 * c1 + ps1;
#pragma unroll
        for (int dt = 0; dt < 8; dt++) {
            oacc[dt][0] *= c0; oacc[dt][1] *= c0;
            oacc[dt][2] *= c1; oacc[dt][3] *= c1;
        }
        m0 = mn0; m1 = mn1;
#pragma unroll
        for (int ks = 0; ks < 4; ks++) {
            uint32_t pa0 = pu01[2 * ks], pa1 = pu23[2 * ks];
            uint32_t pa2 = pu01[2 * ks + 1], pa3 = pu23[2 * ks + 1];
            uint32_t vrow = (uint32_t)(ks * 16) * 128 + v_rowb;
#pragma unroll
            for (int dt2 = 0; dt2 < 4; dt2++) {
                uint32_t vv4[4];
                ldsm_x4t(vv4, Vb + vrow + ((((uint32_t)(dt2 * 2 + hi16)) * 16) ^ xv));
                mma_f16(oacc[2 * dt2],     pa0, pa1, pa2, pa3, vv4[0], vv4[1]);
                mma_f16(oacc[2 * dt2 + 1], pa0, pa1, pa2, pa3, vv4[2], vv4[3]);
            }
        }
        __syncthreads();
    }

    float i0 = 1.f / l0, i1 = 1.f / l1;
    int b = bh >> 4, h = bh & 15;
    int gq0 = qglob + qrow, gq1 = gq0 + 8;
#pragma unroll
    for (int dt = 0; dt < 8; dt++) {
        int d = h * HS + dt * 8 + 2 * tq;
        *(uint32_t*)(g_attn + ((size_t)b * TT + gq0) * DD + d) =
            h2u(oacc[dt][0] * i0, oacc[dt][1] * i0);
        *(uint32_t*)(g_attn + ((size_t)b * TT + gq1) * DD + d) =
            h2u(oacc[dt][2] * i1, oacc[dt][3] * i1);
    }
}

// ---------------- final LN+residual ----------------
__device__ __forceinline__ float4 block_reduce4(float4 v) {
    __shared__ float4 sh[8];
    __shared__ float4 bc;
    int lane = threadIdx.x & 31, w = threadIdx.x >> 5;
#pragma unroll
    for (int off = 16; off; off >>= 1) {
        v.x += __shfl_xor_sync(0xffffffffu, v.x, off);
        v.y += __shfl_xor_sync(0xffffffffu, v.y, off);
        v.z += __shfl_xor_sync(0xffffffffu, v.z, off);
        v.w += __shfl_xor_sync(0xffffffffu, v.w, off);
    }
    if (lane == 0) sh[w] = v;
    __syncthreads();
    if (w == 0) {
        float4 t = (lane < 8) ? sh[lane] : make_float4(0, 0, 0, 0);
#pragma unroll
        for (int off = 4; off; off >>= 1) {
            t.x += __shfl_xor_sync(0xffffffffu, t.x, off);
            t.y += __shfl_xor_sync(0xffffffffu, t.y, off);
            t.z += __shfl_xor_sync(0xffffffffu, t.z, off);
            t.w += __shfl_xor_sync(0xffffffffu, t.w, off);
        }
        if (lane == 0) bc = t;
    }
    __syncthreads();
    return bc;
}

__global__ __launch_bounds__(256) void final_kernel(
    const float* __restrict__ X,
    const float* __restrict__ g1, const float* __restrict__ be1,
    const float* __restrict__ g2, const float* __restrict__ be2,
    float* __restrict__ out)
{
    int t = blockIdx.x;
    int tid = threadIdx.x;
    const __half* ar = g_attn + (size_t)t * DD;
    const __half* y0 = g_y + (size_t)(t * 2) * DD;
    const __half* y1 = g_y + (size_t)(t * 2 + 1) * DD;
    float w0 = g_wtok[t * 2], w1 = g_wtok[t * 2 + 1];

    uint2 ua = *(const uint2*)(ar + tid * 4);
    uint2 u0 = *(const uint2*)(y0 + tid * 4);
    uint2 u1 = *(const uint2*)(y1 + tid * 4);
    float2 aa = __half22float2(*(__half2*)&ua.x);
    float2 ab = __half22float2(*(__half2*)&ua.y);
    float2 y0a = __half22float2(*(__half2*)&u0.x);
    float2 y0b = __half22float2(*(__half2*)&u0.y);
    float2 y1a = __half22float2(*(__half2*)&u1.x);
    float2 y1b = __half22float2(*(__half2*)&u1.y);
    float a[4] = {aa.x, aa.y, ab.x, ab.y};
    float m[4] = {w0 * y0a.x + w1 * y1a.x, w0 * y0a.y + w1 * y1a.y,
                  w0 * y0b.x + w1 * y1b.x, w0 * y0b.y + w1 * y1b.y};

    float4 s = make_float4(0, 0, 0, 0);
#pragma unroll
    for (int j = 0; j < 4; j++) {
        s.x += a[j]; s.y += a[j] * a[j];
        s.z += m[j]; s.w += m[j] * m[j];
    }
    s = block_reduce4(s);
    const float invD = 1.0f / (float)DD;
    float mua = s.x * invD;
    float vara = fmaxf(s.y * invD - mua * mua, 0.f);
    float rsa = rsqrtf(vara + LN_EPS);
    float mum = s.z * invD;
    float varm = fmaxf(s.w * invD - mum * mum, 0.f);
    float rsm = rsqrtf(varm + LN_EPS);

    float4 x4 = ((const float4*)(X + (size_t)t * DD))[tid];
    float4 g14 = ((const float4*)g1)[tid];
    float4 b14 = ((const float4*)be1)[tid];
    float4 g24 = ((const float4*)g2)[tid];
    float4 b24 = ((const float4*)be2)[tid];
    float xs[4] = {x4.x, x4.y, x4.z, x4.w};
    float g1s[4] = {g14.x, g14.y, g14.z, g14.w};
    float b1s[4] = {b14.x, b14.y, b14.z, b14.w};
    float g2s[4] = {g24.x, g24.y, g24.z, g24.w};
    float b2s[4] = {b24.x, b24.y, b24.z, b24.w};
    float o[4];
#pragma unroll
    for (int j = 0; j < 4; j++) {
        o[j] = xs[j]
             + (a[j] - mua) * rsa * g1s[j] + b1s[j]
             + (m[j] - mum) * rsm * g2s[j] + b2s[j];
    }
    ((float4*)(out + (size_t)t * DD))[tid] = make_float4(o[0], o[1], o[2], o[3]);
}

// ---------------- launch: fork/join two streams inside capture ----------------
extern "C" void kernel_launch(void* const* d_in, const int* in_sizes, int n_in,
                              void* d_out, int out_size)
{
    const float* x   = (const float*)d_in[0];
    const float* Wq  = (const float*)d_in[1];
    const float* Wk  = (const float*)d_in[2];
    const float* Wv  = (const float*)d_in[3];
    const float* Wg  = (const float*)d_in[4];
    const float* W1  = (const float*)d_in[5];
    const float* b1  = (const float*)d_in[6];
    const float* W2  = (const float*)d_in[7];
    const float* b2  = (const float*)d_in[8];
    const float* g1  = (const float*)d_in[9];
    const float* be1 = (const float*)d_in[10];
    const float* g2  = (const float*)d_in[11];
    const float* be2 = (const float*)d_in[12];
    float* out = (float*)d_out;

    static cudaStream_t s1 = nullptr;
    static cudaEvent_t ev0 = nullptr, evX = nullptr, evB = nullptr;
    if (s1 == nullptr) {
        cudaStreamCreateWithFlags(&s1, cudaStreamNonBlocking);
        cudaEventCreateWithFlags(&ev0, cudaEventDisableTiming);
        cudaEventCreateWithFlags(&evX, cudaEventDisableTiming);
        cudaEventCreateWithFlags(&evB, cudaEventDisableTiming);
        cudaFuncSetAttribute(qkv_tc_kernel, cudaFuncAttributeMaxDynamicSharedMemorySize, GEMM_SMEM);
        cudaFuncSetAttribute(moe_tc_kernel<true>, cudaFuncAttributeMaxDynamicSharedMemorySize, GEMM_SMEM);
        cudaFuncSetAttribute(moe_tc_kernel<false>, cudaFuncAttributeMaxDynamicSharedMemorySize, GEMM_SMEM);
        cudaFuncSetAttribute(attn_tc_kernel, cudaFuncAttributeMaxDynamicSharedMemorySize, ATT_SMEM);
    }

    __half* d_w1; cudaGetSymbolAddress((void**)&d_w1, g_w1);
    __half* d_w2; cudaGetSymbolAddress((void**)&d_w2, g_w2);
    __half* d_wqkv; cudaGetSymbolAddress((void**)&d_wqkv, g_wqkv);

    const size_t WQKV1 = (size_t)HH * DD * HS;   // 1M elems per part
    const size_t WEXP  = (size_t)NE * DD * DFF;  // 33.5M elems

    // fork: stream B handles expert-weight cvts immediately
    cudaEventRecord(ev0, 0);
    cudaStreamWaitEvent(s1, ev0, 0);
    wcvt_kernel<<<(int)(WEXP / 2048), 256, 0, s1>>>(W1, d_w1);
    wcvt_kernel<<<(int)(WEXP / 2048), 256, 0, s1>>>(W2, d_w2);

    // stream A: counters -> fused route+xcvt
    zcnt_kernel<<<1, 32>>>();
    routex_kernel<<<NTOK / 8, 256>>>(x, Wg);
    cudaEventRecord(evX, 0);

    // stream B: MoE GEMM chain
    cudaStreamWaitEvent(s1, evX, 0);
    moe_tc_kernel<true><<<dim3(64, DFF / 128, NE), 128, GEMM_SMEM, s1>>>(b1);
    moe_tc_kernel<false><<<dim3(64, DD / 128, NE), 128, GEMM_SMEM, s1>>>(b2);
    cudaEventRecord(evB, s1);

    // stream A: QKV + attention
    wcvt_qkv_kernel<<<dim3((int)(WQKV1 / 2048), 3), 256>>>(Wq, Wk, Wv, d_wqkv);
    qkv_tc_kernel<<<dim3(NTOK / 128, 24), 128, GEMM_SMEM>>>();
    attn_tc_kernel<<<dim3(16, BB * HH), 128, ATT_SMEM>>>();

    // join and finish
    cudaStreamWaitEvent(0, evB, 0);
    final_kernel<<<NTOK, 256>>>(x, g1, be1, g2, be2, out);
}

// round 17
// speedup vs baseline: 1.0943x; 1.0943x over previous
#include <cuda_runtime.h>
#include <cuda_fp16.h>
#include <cstdint>
#include <math.h>

#define BB 8
#define TT 1024
#define DD 1024
#define HH 16
#define HS 64
#define NE 8
#define NTOK (BB*TT)        // 8192
#define DFF 4096
#define LN_EPS 1e-5f

// ---------------- scratch (device globals; no runtime allocation) ----------------
__device__ __half g_q[(size_t)BB*HH*TT*HS];      // fp16, Q pre-scaled by 2^-5
__device__ __half g_k[(size_t)BB*HH*TT*HS];
__device__ __half g_v[(size_t)BB*HH*TT*HS];
__device__ __half g_attn[(size_t)NTOK*DD];       // fp16 attention output
__device__ __half g_h[(size_t)NTOK*2*DFF];       // fp16 (post-relu), rowid = tok*2+slot
__device__ __half g_y[(size_t)NTOK*2*DD];        // fp16 expert outputs
__device__ float  g_wtok[NTOK*2];
__device__ int    g_rows[NE*NTOK];
__device__ int    g_cnt[NE];
__device__ __half g_xt[(size_t)NTOK*DD];         // fp16 of x
__device__ __half g_w1[(size_t)NE*DD*DFF];       // W1 fp16, native [e][k][n]
__device__ __half g_w2[(size_t)NE*DFF*DD];       // W2 fp16, native [e][k][n]
__device__ __half g_wqkv[(size_t)3*HH*DD*HS];    // native [part][h][k][hs] fp16

// ---------------- helpers ----------------
__device__ __forceinline__ uint32_t smem_u32(const void* p) {
    uint32_t a;
    asm("{ .reg .u64 t; cvta.to.shared.u64 t, %1; cvt.u32.u64 %0, t; }" : "=r"(a) : "l"(p));
    return a;
}
#define SWZ(b) ((b) ^ (((b) >> 3) & 0x70))

__device__ __forceinline__ void mma_f16(float* c,
    uint32_t a0, uint32_t a1, uint32_t a2, uint32_t a3,
    uint32_t b0, uint32_t b1)
{
    asm volatile(
        "mma.sync.aligned.m16n8k16.row.col.f32.f16.f16.f32 "
        "{%0,%1,%2,%3}, {%4,%5,%6,%7}, {%8,%9}, {%0,%1,%2,%3};"
        : "+f"(c[0]), "+f"(c[1]), "+f"(c[2]), "+f"(c[3])
        : "r"(a0), "r"(a1), "r"(a2), "r"(a3), "r"(b0), "r"(b1));
}
__device__ __forceinline__ void ldsm_x4(uint32_t* r, uint32_t addr) {
    asm volatile("ldmatrix.sync.aligned.m8n8.x4.shared.b16 {%0,%1,%2,%3}, [%4];"
        : "=r"(r[0]), "=r"(r[1]), "=r"(r[2]), "=r"(r[3]) : "r"(addr));
}
__device__ __forceinline__ void ldsm_x2t(uint32_t* r, uint32_t addr) {
    asm volatile("ldmatrix.sync.aligned.m8n8.x2.trans.shared.b16 {%0,%1}, [%2];"
        : "=r"(r[0]), "=r"(r[1]) : "r"(addr));
}
__device__ __forceinline__ void ldsm_x4t(uint32_t* r, uint32_t addr) {
    asm volatile("ldmatrix.sync.aligned.m8n8.x4.trans.shared.b16 {%0,%1,%2,%3}, [%4];"
        : "=r"(r[0]), "=r"(r[1]), "=r"(r[2]), "=r"(r[3]) : "r"(addr));
}
#define CP_ASYNC16(dst, src) \
    asm volatile("cp.async.cg.shared.global [%0], [%1], 16;" :: "r"(dst), "l"((const void*)(src)))
#define CP_COMMIT() asm volatile("cp.async.commit_group;" ::: "memory")
#define CP_WAIT1() asm volatile("cp.async.wait_group 1;" ::: "memory")

__device__ __forceinline__ uint32_t h2u(float a, float b) {
    __half2 h = __floats2half2_rn(a, b);
    return *(uint32_t*)&h;
}
__device__ __forceinline__ uint32_t exp2_f16x2(float a, float b) {
    __half2 h = __floats2half2_rn(a, b);
    uint32_t u = *(uint32_t*)&h, r;
    asm("ex2.approx.f16x2 %0, %1;" : "=r"(r) : "r"(u));
    return r;
}

// GEMM smem: 3 stages x (A 16KB + B 16KB) = 96KB
#define ST_BYTES 16384
#define GEMM_SMEM (6 * ST_BYTES + 1024)

// ---------------- preprocessing ----------------
__global__ void zcnt_kernel() {
    if (threadIdx.x < NE) g_cnt[threadIdx.x] = 0;
}

// streaming fp32 -> fp16 copy, 8 elems/thread
__global__ __launch_bounds__(256) void wcvt_kernel(
    const float* __restrict__ in, __half* __restrict__ out)
{
    size_t i = ((size_t)blockIdx.x * 256 + threadIdx.x) * 8;
    float4 v0 = *(const float4*)(in + i);
    float4 v1 = *(const float4*)(in + i + 4);
    uint4 u = make_uint4(h2u(v0.x, v0.y), h2u(v0.z, v0.w),
                         h2u(v1.x, v1.y), h2u(v1.z, v1.w));
    *(uint4*)(out + i) = u;
}

// QKV weights: 3 parts in one launch, grid (512, 3)
__global__ __launch_bounds__(256) void wcvt_qkv_kernel(
    const float* __restrict__ Wq, const float* __restrict__ Wk,
    const float* __restrict__ Wv, __half* __restrict__ out)
{
    const size_t PART = (size_t)HH * DD * HS;
    int part = blockIdx.y;
    const float* in = (part == 0) ? Wq : (part == 1) ? Wk : Wv;
    size_t i = ((size_t)blockIdx.x * 256 + threadIdx.x) * 8;
    float4 v0 = *(const float4*)(in + i);
    float4 v1 = *(const float4*)(in + i + 4);
    uint4 u = make_uint4(h2u(v0.x, v0.y), h2u(v0.z, v0.w),
                         h2u(v1.x, v1.y), h2u(v1.z, v1.w));
    *(uint4*)(out + part * PART + i) = u;
}

// ---------------- fused routing + x cvt: warp per token, Wg smem-transposed ----
__global__ __launch_bounds__(256) void routex_kernel(
    const float* __restrict__ X, const float* __restrict__ Wg)
{
    __shared__ float4 wgt[NE][256];   // WgT: [e][d/4] float4, 32KB
    const int tid = threadIdx.x;
    const float4* Wg4 = (const float4*)Wg;
#pragma unroll
    for (int i = 0; i < 8; i++) {
        int fi = tid + i * 256;            // 0..2047
        float4 v = Wg4[fi];
        int d = fi >> 1;
        int e0 = (fi & 1) * 4;
        int q = d >> 2, c = d & 3;
        ((float*)&wgt[e0 + 0][q])[c] = v.x;
        ((float*)&wgt[e0 + 1][q])[c] = v.y;
        ((float*)&wgt[e0 + 2][q])[c] = v.z;
        ((float*)&wgt[e0 + 3][q])[c] = v.w;
    }
    __syncthreads();

    int tok = (blockIdx.x * 256 + tid) >> 5;
    int lane = tid & 31;
    const float* xr = X + (size_t)tok * DD;
    __half* xo = g_xt + (size_t)tok * DD;
    float p[NE];
#pragma unroll
    for (int e = 0; e < NE; e++) p[e] = 0.f;
#pragma unroll
    for (int it = 0; it < 8; it++) {
        int d4 = lane + it * 32;
        float4 xv = ((const float4*)xr)[d4];
        *(uint2*)(xo + d4 * 4) = make_uint2(h2u(xv.x, xv.y), h2u(xv.z, xv.w));
#pragma unroll
        for (int e = 0; e < NE; e++) {
            float4 w = wgt[e][d4];
            p[e] += xv.x * w.x; p[e] += xv.y * w.y;
            p[e] += xv.z * w.z; p[e] += xv.w * w.w;
        }
    }
#pragma unroll
    for (int e = 0; e < NE; e++)
#pragma unroll
        for (int off = 16; off; off >>= 1)
            p[e] += __shfl_xor_sync(0xffffffffu, p[e], off);

    if (lane == 0) {
        int i0 = 0; float v0 = p[0];
#pragma unroll
        for (int e = 1; e < NE; e++) if (p[e] > v0) { v0 = p[e]; i0 = e; }
        int i1 = -1; float v1 = -INFINITY;
#pragma unroll
        for (int e = 0; e < NE; e++) if (e != i0 && p[e] > v1) { v1 = p[e]; i1 = e; }
        float e1v = expf(v1 - v0);
        float inv = 1.f / (1.f + e1v);
        g_wtok[tok * 2 + 0] = inv;
        g_wtok[tok * 2 + 1] = e1v * inv;
        int pos0 = atomicAdd(&g_cnt[i0], 1);
        g_rows[i0 * NTOK + pos0] = tok * 2;
        int pos1 = atomicAdd(&g_cnt[i1], 1);
        g_rows[i1 * NTOK + pos1] = tok * 2 + 1;
    }
}

// =======================================================================
// QKV GEMM: grid (64, 24), block 128 (4 warps, 64x64 warp tiles)
// R15-proven inner loop: x2t B frags, two barriers per chunk
// =======================================================================
__global__ __launch_bounds__(128) void qkv_tc_kernel()
{
    const int row0 = blockIdx.x * 128;
    const int by = blockIdx.y;
    const int part = by >> 3;
    const int h0 = (by & 7) * 2;
    __half* Out = (part == 0) ? g_q : (part == 1) ? g_k : g_v;
    const float qscale = (part == 0) ? 0.03125f : 1.0f;

    extern __shared__ char dynraw[];
    char* p = (char*)(((uintptr_t)dynraw + 1023) & ~(uintptr_t)1023);
    const uint32_t sb = smem_u32(p);
    const int tid = threadIdx.x;
    const int wid = tid >> 5, lane = tid & 31;
    const int wm = (wid & 1) * 64, wn = (wid >> 1) * 64;

    const int quad = lane >> 3, lr = lane & 7;
    const uint32_t a_rowb = (uint32_t)(wm + (quad & 1) * 8 + lr) * 128;
    const uint32_t a_boff = (uint32_t)(quad >> 1) * 16;
    const uint32_t xv = (uint32_t)lr << 4;
    const uint32_t bt_row = (uint32_t)(((lane >> 3) & 1) * 8 + lr) * 128;

    float acc[4][8][4];
#pragma unroll
    for (int i = 0; i < 4; i++)
#pragma unroll
        for (int j = 0; j < 8; j++)
#pragma unroll
            for (int q = 0; q < 4; q++) acc[i][j][q] = 0.f;

    const int NCH = DD / 64;
    auto issue = [&](int c) {
        int k0 = c * 64;
        int s = c % 3;
        uint32_t ab = sb + s * ST_BYTES;
        uint32_t bb = sb + 3 * ST_BYTES + s * ST_BYTES;
#pragma unroll
        for (int i = 0; i < 8; i++) {
            int idx = tid + i * 128;
            {
                int row = idx >> 3, c16 = idx & 7;
                const __half* asrc = g_xt + (size_t)(row0 + row) * DD + k0 + c16 * 8;
                CP_ASYNC16(ab + SWZ(row * 128 + c16 * 16), asrc);
            }
            {
                int sub = idx >> 9, rem = idx & 511;
                int r = rem >> 3, c16 = rem & 7;
                const __half* bsrc = g_wqkv +
                    ((size_t)(part * HH + h0 + sub) * DD + k0 + r) * HS + c16 * 8;
                CP_ASYNC16(bb + sub * 8192 + SWZ(r * 128 + c16 * 16), bsrc);
            }
        }
        CP_COMMIT();
    };
    issue(0); issue(1);

    for (int c = 0; c < NCH; c++) {
        CP_WAIT1();
        __syncthreads();
        if (c + 2 < NCH) issue(c + 2); else CP_COMMIT();
        const int s = c % 3;
        const uint32_t At = sb + s * ST_BYTES;
        const uint32_t Bt = sb + 3 * ST_BYTES + s * ST_BYTES;
#pragma unroll
        for (int ks = 0; ks < 4; ks++) {
            uint32_t akoff = (((uint32_t)ks * 32) + a_boff) ^ xv;
            uint32_t trow = (uint32_t)(ks * 16) * 128 + bt_row;
            uint32_t af[4][4], bf[8][2];
#pragma unroll
            for (int mt = 0; mt < 4; mt++)
                ldsm_x4(af[mt], At + a_rowb + mt * 2048 + akoff);
#pragma unroll
            for (int nt = 0; nt < 8; nt++) {
                int gn = wn + nt * 8;
                uint32_t sub = (uint32_t)(gn >> 6) * 8192;
                uint32_t cb = (uint32_t)((gn & 63) * 2);
                ldsm_x2t(bf[nt], Bt + sub + trow + (cb ^ xv));
            }
#pragma unroll
            for (int mt = 0; mt < 4; mt++)
#pragma unroll
                for (int nt = 0; nt < 8; nt++)
                    mma_f16(acc[mt][nt], af[mt][0], af[mt][1], af[mt][2], af[mt][3],
                            bf[nt][0], bf[nt][1]);
        }
        __syncthreads();
    }

#pragma unroll
    for (int mt = 0; mt < 4; mt++) {
        int r = row0 + wm + mt * 16 + (lane >> 2);
        int r1 = r + 8;
        int b0i = r >> 10, t0 = r & 1023;
        int b1i = r1 >> 10, t1 = r1 & 1023;
#pragma unroll
        for (int nt = 0; nt < 8; nt++) {
            int n = wn + nt * 8 + 2 * (lane & 3);
            int head = h0 + (n >> 6);
            int hs = n & 63;
            *(uint32_t*)(Out + (((size_t)b0i * HH + head) * TT + t0) * HS + hs) =
                h2u(acc[mt][nt][0] * qscale, acc[mt][nt][1] * qscale);
            *(uint32_t*)(Out + (((size_t)b1i * HH + head) * TT + t1) * HS + hs) =
                h2u(acc[mt][nt][2] * qscale, acc[mt][nt][3] * qscale);
        }
    }
}

// =======================================================================
// MoE GEMM (G1: xt@W1+relu -> g_h fp16, else g_h@W2 -> g_y fp16)
// grid (64, Ntiles, NE), block 128; R15-proven inner loop
// =======================================================================
template<bool G1>
__global__ __launch_bounds__(128) void moe_tc_kernel(
    const float* __restrict__ biasfull)
{
    const int e = blockIdx.z;
    const int cnt = g_cnt[e];
    const int m0 = blockIdx.x * 128;
    if (m0 >= cnt) return;
    const int col0 = blockIdx.y * 128;
    const int KTOT = G1 ? DD : DFF;
    const int LDB  = G1 ? DFF : DD;
    const int LDO  = G1 ? DFF : DD;
    const int NCH = KTOT / 64;

    extern __shared__ char dynraw[];
    char* p = (char*)(((uintptr_t)dynraw + 1023) & ~(uintptr_t)1023);
    const uint32_t sb = smem_u32(p);

    __shared__ int rowids[128];
    const int tid = threadIdx.x;
    {
        int m = m0 + tid;
        rowids[tid] = (m < cnt) ? g_rows[e * NTOK + m] : -1;
    }
    __syncthreads();

    const int wid = tid >> 5, lane = tid & 31;
    const int wm = (wid & 1) * 64, wn = (wid >> 1) * 64;
    const int quad = lane >> 3, lr = lane & 7;
    const uint32_t a_rowb = (uint32_t)(wm + (quad & 1) * 8 + lr) * 128;
    const uint32_t a_boff = (uint32_t)(quad >> 1) * 16;
    const uint32_t xv = (uint32_t)lr << 4;
    const uint32_t bt_row = (uint32_t)(((lane >> 3) & 1) * 8 + lr) * 128;

    float acc[4][8][4];
#pragma unroll
    for (int i = 0; i < 4; i++)
#pragma unroll
        for (int j = 0; j < 8; j++)
#pragma unroll
            for (int q = 0; q < 4; q++) acc[i][j][q] = 0.f;

    const __half* Wp = (G1 ? g_w1 : g_w2) + (size_t)e * ((size_t)DD * DFF);
    const float* bp = biasfull + (size_t)e * (G1 ? DFF : DD);

    auto issue = [&](int c) {
        int k0 = c * 64;
        int s = c % 3;
        uint32_t ab = sb + s * ST_BYTES;
        uint32_t bb = sb + 3 * ST_BYTES + s * ST_BYTES;
#pragma unroll
        for (int i = 0; i < 8; i++) {
            int idx = tid + i * 128;
            {
                int row = idx >> 3, c16 = idx & 7;
                int rid = rowids[row];
                const __half* asrc;
                if (G1) asrc = g_xt + (size_t)((rid >= 0) ? (rid >> 1) : 0) * DD + k0 + c16 * 8;
                else    asrc = g_h + (size_t)((rid >= 0) ? rid : 0) * DFF + k0 + c16 * 8;
                CP_ASYNC16(ab + SWZ(row * 128 + c16 * 16), asrc);
            }
            {
                int sub = idx >> 9, rem = idx & 511;
                int r = rem >> 3, c16 = rem & 7;
                const __half* bsrc = Wp + (size_t)(k0 + r) * LDB + col0 + sub * 64 + c16 * 8;
                CP_ASYNC16(bb + sub * 8192 + SWZ(r * 128 + c16 * 16), bsrc);
            }
        }
        CP_COMMIT();
    };
    issue(0); issue(1);

    for (int c = 0; c < NCH; c++) {
        CP_WAIT1();
        __syncthreads();
        if (c + 2 < NCH) issue(c + 2); else CP_COMMIT();
        const int s = c % 3;
        const uint32_t At = sb + s * ST_BYTES;
        const uint32_t Bt = sb + 3 * ST_BYTES + s * ST_BYTES;
#pragma unroll
        for (int ks = 0; ks < 4; ks++) {
            uint32_t akoff = (((uint32_t)ks * 32) + a_boff) ^ xv;
            uint32_t trow = (uint32_t)(ks * 16) * 128 + bt_row;
            uint32_t af[4][4], bf[8][2];
#pragma unroll
            for (int mt = 0; mt < 4; mt++)
                ldsm_x4(af[mt], At + a_rowb + mt * 2048 + akoff);
#pragma unroll
            for (int nt = 0; nt < 8; nt++) {
                int gn = wn + nt * 8;
                uint32_t sub = (uint32_t)(gn >> 6) * 8192;
                uint32_t cb = (uint32_t)((gn & 63) * 2);
                ldsm_x2t(bf[nt], Bt + sub + trow + (cb ^ xv));
            }
#pragma unroll
            for (int mt = 0; mt < 4; mt++)
#pragma unroll
                for (int nt = 0; nt < 8; nt++)
                    mma_f16(acc[mt][nt], af[mt][0], af[mt][1], af[mt][2], af[mt][3],
                            bf[nt][0], bf[nt][1]);
        }
        __syncthreads();
    }

#pragma unroll
    for (int mt = 0; mt < 4; mt++) {
        int ml = wm + mt * 16 + (lane >> 2);
        int rid0 = rowids[ml];
        int rid1 = rowids[ml + 8];
#pragma unroll
        for (int nt = 0; nt < 8; nt++) {
            int n = col0 + wn + nt * 8 + 2 * (lane & 3);
            float bx = __ldg(&bp[n]), by = __ldg(&bp[n + 1]);
            if (G1) {
                if (rid0 >= 0) {
                    float v0 = fmaxf(acc[mt][nt][0] + bx, 0.f);
                    float v1 = fmaxf(acc[mt][nt][1] + by, 0.f);
                    *(uint32_t*)(g_h + (size_t)rid0 * LDO + n) = h2u(v0, v1);
                }
                if (rid1 >= 0) {
                    float v2 = fmaxf(acc[mt][nt][2] + bx, 0.f);
                    float v3 = fmaxf(acc[mt][nt][3] + by, 0.f);
                    *(uint32_t*)(g_h + (size_t)rid1 * LDO + n) = h2u(v2, v3);
                }
            } else {
                if (rid0 >= 0)
                    *(uint32_t*)(g_y + (size_t)rid0 * LDO + n) =
                        h2u(acc[mt][nt][0] + bx, acc[mt][nt][1] + by);
                if (rid1 >= 0)
                    *(uint32_t*)(g_y + (size_t)rid1 * LDO + n) =
                        h2u(acc[mt][nt][2] + bx, acc[mt][nt][3] + by);
            }
        }
    }
}

// =======================================================================
// fp16 tensor-core causal flash attention (R15: P in regs, K/V x4)
// =======================================================================
#define ATT_SMEM (8192 + 2 * 16384)
#define L2E 1.44269504f

__global__ __launch_bounds__(128) void attn_tc_kernel()
{
    extern __shared__ char asc[];
    const uint32_t psb = smem_u32(asc);
    const uint32_t kvb = psb + 8192;

    const int bh = blockIdx.y;
    const int qt = 15 - blockIdx.x;
    const int tid = threadIdx.x;
    const int wid = tid >> 5, lane = tid & 31;
    const int gid = lane >> 2, tq = lane & 3;
    const int quad = lane >> 3, lr = lane & 7;
    const int qrow = wid * 16 + gid;
    const int qglob = qt * 64;

    const uint32_t a_rowb = (uint32_t)(wid * 16 + (quad & 1) * 8 + lr) * 128;
    const uint32_t a_boff = (uint32_t)(quad >> 1) * 16;
    const uint32_t b_boff = (uint32_t)((lane >> 3) & 1) * 16;
    const uint32_t xv = (uint32_t)lr << 4;
    const uint32_t hi16 = (uint32_t)((lane >> 4) & 1);
    const uint32_t kx_rowb = (hi16 * 8 + (uint32_t)lr) * 128;
    const uint32_t v_rowb = ((uint32_t)((lane >> 3) & 1) * 8 + (uint32_t)lr) * 128;

    auto issue_kv = [&](int kt) {
        int s = kt & 1;
        uint32_t kb = kvb + s * 16384;
        uint32_t vb = kb + 8192;
        const __half* kp = g_k + ((size_t)bh * TT + kt * 64) * HS;
        const __half* vp = g_v + ((size_t)bh * TT + kt * 64) * HS;
#pragma unroll
        for (int i = 0; i < 4; i++) {
            int idx = tid + i * 128;
            int r = idx >> 3, c16 = idx & 7;
            CP_ASYNC16(kb + SWZ(r * 128 + c16 * 16), kp + (size_t)r * HS + c16 * 8);
            CP_ASYNC16(vb + SWZ(r * 128 + c16 * 16), vp + (size_t)r * HS + c16 * 8);
        }
        CP_COMMIT();
    };

    {
        const __half* qp = g_q + ((size_t)bh * TT + qglob) * HS;
#pragma unroll
        for (int i = 0; i < 4; i++) {
            int idx = tid + i * 128;
            int r = idx >> 3, c16 = idx & 7;
            CP_ASYNC16(psb + SWZ(r * 128 + c16 * 16), qp + (size_t)r * HS + c16 * 8);
        }
        CP_COMMIT();
    }
    issue_kv(0);
    CP_WAIT1();
    __syncthreads();

    uint32_t qf[4][4];
#pragma unroll
    for (int ks = 0; ks < 4; ks++)
        ldsm_x4(qf[ks], psb + a_rowb + ((((uint32_t)ks * 32) + a_boff) ^ xv));

    float oacc[8][4];
#pragma unroll
    for (int i = 0; i < 8; i++)
#pragma unroll
        for (int j = 0; j < 4; j++) oacc[i][j] = 0.f;
    float m0 = -INFINITY, m1 = -INFINITY, l0 = 0.f, l1 = 0.f;

    for (int kt = 0; kt <= qt; kt++) {
        if (kt + 1 <= qt) issue_kv(kt + 1); else CP_COMMIT();
        CP_WAIT1();
        __syncthreads();
        const int s = kt & 1;
        const uint32_t Kb = kvb + s * 16384;
        const uint32_t Vb = Kb + 8192;

        float sacc[8][4];
#pragma unroll
        for (int nt = 0; nt < 8; nt++)
#pragma unroll
            for (int j = 0; j < 4; j++) sacc[nt][j] = 0.f;
#pragma unroll
        for (int ks = 0; ks < 4; ks++) {
            uint32_t bkoff = (((uint32_t)ks * 32) + b_boff) ^ xv;
#pragma unroll
            for (int nt2 = 0; nt2 < 4; nt2++) {
                uint32_t bf4[4];
                ldsm_x4(bf4, Kb + (uint32_t)(nt2 * 16) * 128 + kx_rowb + bkoff);
                mma_f16(sacc[2 * nt2],     qf[ks][0], qf[ks][1], qf[ks][2], qf[ks][3],
                        bf4[0], bf4[1]);
                mma_f16(sacc[2 * nt2 + 1], qf[ks][0], qf[ks][1], qf[ks][2], qf[ks][3],
                        bf4[2], bf4[3]);
            }
        }
        if (kt == qt) {
#pragma unroll
            for (int nt = 0; nt < 8; nt++) {
                int col = nt * 8 + 2 * tq;
                if (col     > qrow)     sacc[nt][0] = -INFINITY;
                if (col + 1 > qrow)     sacc[nt][1] = -INFINITY;
                if (col     > qrow + 8) sacc[nt][2] = -INFINITY;
                if (col + 1 > qrow + 8) sacc[nt][3] = -INFINITY;
            }
        }
        float r0 = -INFINITY, r1 = -INFINITY;
#pragma unroll
        for (int nt = 0; nt < 8; nt++) {
            r0 = fmaxf(r0, fmaxf(sacc[nt][0], sacc[nt][1]));
            r1 = fmaxf(r1, fmaxf(sacc[nt][2], sacc[nt][3]));
        }
        r0 = fmaxf(r0, __shfl_xor_sync(0xffffffffu, r0, 1));
        r0 = fmaxf(r0, __shfl_xor_sync(0xffffffffu, r0, 2));
        r1 = fmaxf(r1, __shfl_xor_sync(0xffffffffu, r1, 1));
        r1 = fmaxf(r1, __shfl_xor_sync(0xffffffffu, r1, 2));
        float mn0 = fmaxf(m0, r0), mn1 = fmaxf(m1, r1);
        float c0 = __expf(m0 - mn0), c1 = __expf(m1 - mn1);
        float ps0 = 0.f, ps1 = 0.f;
        uint32_t pu01[8], pu23[8];
#pragma unroll
        for (int nt = 0; nt < 8; nt++) {
            pu01[nt] = exp2_f16x2((sacc[nt][0] - mn0) * L2E, (sacc[nt][1] - mn0) * L2E);
            pu23[nt] = exp2_f16x2((sacc[nt][2] - mn1) * L2E, (sacc[nt][3] - mn1) * L2E);
            float2 f01 = __half22float2(*(__half2*)&pu01[nt]);
            float2 f23 = __half22float2(*(__half2*)&pu23[nt]);
            ps0 += f01.x + f01.y;
            ps1 += f23.x + f23.y;
        }
        ps0 += __shfl_xor_sync(0xffffffffu, ps0, 1);
        ps0 += __shfl_xor_sync(0xffffffffu, ps0, 2);
        ps1 += __shfl_xor_sync(0xffffffffu, ps1, 1);
        ps1 += __shfl_xor_sync(0xffffffffu, ps1, 2);
        l0 = l0 * c0 + ps0;
        l1 = l1 * c1 + ps1;
#pragma unroll
        for (int dt = 0; dt < 8; dt++) {
            oacc[dt][0] *= c0; oacc[dt][1] *= c0;
            oacc[dt][2] *= c1; oacc[dt][3] *= c1;
        }
        m0 = mn0; m1 = mn1;
#pragma unroll
        for (int ks = 0; ks < 4; ks++) {
            uint32_t pa0 = pu01[2 * ks], pa1 = pu23[2 * ks];
            uint32_t pa2 = pu01[2 * ks + 1], pa3 = pu23[2 * ks + 1];
            uint32_t vrow = (uint32_t)(ks * 16) * 128 + v_rowb;
#pragma unroll
            for (int dt2 = 0; dt2 < 4; dt2++) {
                uint32_t vv4[4];
                ldsm_x4t(vv4, Vb + vrow + ((((uint32_t)(dt2 * 2 + hi16)) * 16) ^ xv));
                mma_f16(oacc[2 * dt2],     pa0, pa1, pa2, pa3, vv4[0], vv4[1]);
                mma_f16(oacc[2 * dt2 + 1], pa0, pa1, pa2, pa3, vv4[2], vv4[3]);
            }
        }
        __syncthreads();
    }

    float i0 = 1.f / l0, i1 = 1.f / l1;
    int b = bh >> 4, h = bh & 15;
    int gq0 = qglob + qrow, gq1 = gq0 + 8;
#pragma unroll
    for (int dt = 0; dt < 8; dt++) {
        int d = h * HS + dt * 8 + 2 * tq;
        *(uint32_t*)(g_attn + ((size_t)b * TT + gq0) * DD + d) =
            h2u(oacc[dt][0] * i0, oacc[dt][1] * i0);
        *(uint32_t*)(g_attn + ((size_t)b * TT + gq1) * DD + d) =
            h2u(oacc[dt][2] * i1, oacc[dt][3] * i1);
    }
}

// ---------------- final LN+residual ----------------
__device__ __forceinline__ float4 block_reduce4(float4 v) {
    __shared__ float4 sh[8];
    __shared__ float4 bc;
    int lane = threadIdx.x & 31, w = threadIdx.x >> 5;
#pragma unroll
    for (int off = 16; off; off >>= 1) {
        v.x += __shfl_xor_sync(0xffffffffu, v.x, off);
        v.y += __shfl_xor_sync(0xffffffffu, v.y, off);
        v.z += __shfl_xor_sync(0xffffffffu, v.z, off);
        v.w += __shfl_xor_sync(0xffffffffu, v.w, off);
    }
    if (lane == 0) sh[w] = v;
    __syncthreads();
    if (w == 0) {
        float4 t = (lane < 8) ? sh[lane] : make_float4(0, 0, 0, 0);
#pragma unroll
        for (int off = 4; off; off >>= 1) {
            t.x += __shfl_xor_sync(0xffffffffu, t.x, off);
            t.y += __shfl_xor_sync(0xffffffffu, t.y, off);
            t.z += __shfl_xor_sync(0xffffffffu, t.z, off);
            t.w += __shfl_xor_sync(0xffffffffu, t.w, off);
        }
        if (lane == 0) bc = t;
    }
    __syncthreads();
    return bc;
}

__global__ __launch_bounds__(256) void final_kernel(
    const float* __restrict__ X,
    const float* __restrict__ g1, const float* __restrict__ be1,
    const float* __restrict__ g2, const float* __restrict__ be2,
    float* __restrict__ out)
{
    int t = blockIdx.x;
    int tid = threadIdx.x;
    const __half* ar = g_attn + (size_t)t * DD;
    const __half* y0 = g_y + (size_t)(t * 2) * DD;
    const __half* y1 = g_y + (size_t)(t * 2 + 1) * DD;
    float w0 = g_wtok[t * 2], w1 = g_wtok[t * 2 + 1];

    uint2 ua = *(const uint2*)(ar + tid * 4);
    uint2 u0 = *(const uint2*)(y0 + tid * 4);
    uint2 u1 = *(const uint2*)(y1 + tid * 4);
    float2 aa = __half22float2(*(__half2*)&ua.x);
    float2 ab = __half22float2(*(__half2*)&ua.y);
    float2 y0a = __half22float2(*(__half2*)&u0.x);
    float2 y0b = __half22float2(*(__half2*)&u0.y);
    float2 y1a = __half22float2(*(__half2*)&u1.x);
    float2 y1b = __half22float2(*(__half2*)&u1.y);
    float a[4] = {aa.x, aa.y, ab.x, ab.y};
    float m[4] = {w0 * y0a.x + w1 * y1a.x, w0 * y0a.y + w1 * y1a.y,
                  w0 * y0b.x + w1 * y1b.x, w0 * y0b.y + w1 * y1b.y};

    float4 s = make_float4(0, 0, 0, 0);
#pragma unroll
    for (int j = 0; j < 4; j++) {
        s.x += a[j]; s.y += a[j] * a[j];
        s.z += m[j]; s.w += m[j] * m[j];
    }
    s = block_reduce4(s);
    const float invD = 1.0f / (float)DD;
    float mua = s.x * invD;
    float vara = fmaxf(s.y * invD - mua * mua, 0.f);
    float rsa = rsqrtf(vara + LN_EPS);
    float mum = s.z * invD;
    float varm = fmaxf(s.w * invD - mum * mum, 0.f);
    float rsm = rsqrtf(varm + LN_EPS);

    float4 x4 = ((const float4*)(X + (size_t)t * DD))[tid];
    float4 g14 = ((const float4*)g1)[tid];
    float4 b14 = ((const float4*)be1)[tid];
    float4 g24 = ((const float4*)g2)[tid];
    float4 b24 = ((const float4*)be2)[tid];
    float xs[4] = {x4.x, x4.y, x4.z, x4.w};
    float g1s[4] = {g14.x, g14.y, g14.z, g14.w};
    float b1s[4] = {b14.x, b14.y, b14.z, b14.w};
    float g2s[4] = {g24.x, g24.y, g24.z, g24.w};
    float b2s[4] = {b24.x, b24.y, b24.z, b24.w};
    float o[4];
#pragma unroll
    for (int j = 0; j < 4; j++) {
        o[j] = xs[j]
             + (a[j] - mua) * rsa * g1s[j] + b1s[j]
             + (m[j] - mum) * rsm * g2s[j] + b2s[j];
    }
    ((float4*)(out + (size_t)t * DD))[tid] = make_float4(o[0], o[1], o[2], o[3]);
}

// ---------------- launch: fork/join two streams inside capture ----------------
extern "C" void kernel_launch(void* const* d_in, const int* in_sizes, int n_in,
                              void* d_out, int out_size)
{
    const float* x   = (const float*)d_in[0];
    const float* Wq  = (const float*)d_in[1];
    const float* Wk  = (const float*)d_in[2];
    const float* Wv  = (const float*)d_in[3];
    const float* Wg  = (const float*)d_in[4];
    const float* W1  = (const float*)d_in[5];
    const float* b1  = (const float*)d_in[6];
    const float* W2  = (const float*)d_in[7];
    const float* b2  = (const float*)d_in[8];
    const float* g1  = (const float*)d_in[9];
    const float* be1 = (const float*)d_in[10];
    const float* g2  = (const float*)d_in[11];
    const float* be2 = (const float*)d_in[12];
    float* out = (float*)d_out;

    static cudaStream_t s1 = nullptr;
    static cudaEvent_t ev0 = nullptr, evX = nullptr, evB = nullptr, evW2 = nullptr;
    if (s1 == nullptr) {
        cudaStreamCreateWithFlags(&s1, cudaStreamNonBlocking);
        cudaEventCreateWithFlags(&ev0, cudaEventDisableTiming);
        cudaEventCreateWithFlags(&evX, cudaEventDisableTiming);
        cudaEventCreateWithFlags(&evB, cudaEventDisableTiming);
        cudaEventCreateWithFlags(&evW2, cudaEventDisableTiming);
        cudaFuncSetAttribute(qkv_tc_kernel, cudaFuncAttributeMaxDynamicSharedMemorySize, GEMM_SMEM);
        cudaFuncSetAttribute(moe_tc_kernel<true>, cudaFuncAttributeMaxDynamicSharedMemorySize, GEMM_SMEM);
        cudaFuncSetAttribute(moe_tc_kernel<false>, cudaFuncAttributeMaxDynamicSharedMemorySize, GEMM_SMEM);
        cudaFuncSetAttribute(attn_tc_kernel, cudaFuncAttributeMaxDynamicSharedMemorySize, ATT_SMEM);
    }

    __half* d_w1; cudaGetSymbolAddress((void**)&d_w1, g_w1);
    __half* d_w2; cudaGetSymbolAddress((void**)&d_w2, g_w2);
    __half* d_wqkv; cudaGetSymbolAddress((void**)&d_wqkv, g_wqkv);

    const size_t WQKV1 = (size_t)HH * DD * HS;   // 1M elems per part
    const size_t WEXP  = (size_t)NE * DD * DFF;  // 33.5M elems

    // fork: stream B converts only W1 before the MoE chain
    cudaEventRecord(ev0, 0);
    cudaStreamWaitEvent(s1, ev0, 0);
    wcvt_kernel<<<(int)(WEXP / 2048), 256, 0, s1>>>(W1, d_w1);

    // stream A: counters -> fused route+xcvt, then W2 cvt (for gemm2)
    zcnt_kernel<<<1, 32>>>();
    routex_kernel<<<NTOK / 8, 256>>>(x, Wg);
    cudaEventRecord(evX, 0);
    wcvt_kernel<<<(int)(WEXP / 2048), 256>>>(W2, d_w2);
    cudaEventRecord(evW2, 0);

    // stream B: gemm1 needs W1 + routing; gemm2 additionally needs W2
    cudaStreamWaitEvent(s1, evX, 0);
    moe_tc_kernel<true><<<dim3(64, DFF / 128, NE), 128, GEMM_SMEM, s1>>>(b1);
    cudaStreamWaitEvent(s1, evW2, 0);
    moe_tc_kernel<false><<<dim3(64, DD / 128, NE), 128, GEMM_SMEM, s1>>>(b2);
    cudaEventRecord(evB, s1);

    // stream A: QKV + attention
    wcvt_qkv_kernel<<<dim3((int)(WQKV1 / 2048), 3), 256>>>(Wq, Wk, Wv, d_wqkv);
    qkv_tc_kernel<<<dim3(NTOK / 128, 24), 128, GEMM_SMEM>>>();
    attn_tc_kernel<<<dim3(16, BB * HH), 128, ATT_SMEM>>>();

    // join and finish
    cudaStreamWaitEvent(0, evB, 0);
    final_kernel<<<NTOK, 256>>>(x, g1, be1, g2, be2, out);
}